// round 7
// baseline (speedup 1.0000x reference)
#include <cuda_runtime.h>
#include <math.h>
#include <stdint.h>

// ---------------- problem constants ----------------
namespace la {
constexpr int DIM    = 1024;
constexpr int NHEADS = 16;
constexpr int HD     = 64;
constexpr int NB     = 4;
constexpr int SEQ    = 4096;
constexpr int ROWS   = NB * SEQ; // 16384
constexpr int CHUNK  = 128;
constexpr int NCHUNK = SEQ / CHUNK; // 32
}

// ---------------- scratch (device globals: allocation-free) ----------------
__device__ float g_qkv[(size_t)la::ROWS * 3 * la::DIM];
__device__ float g_attn[(size_t)la::ROWS * la::DIM];
__device__ float g_ckv[(size_t)la::NB * la::NHEADS * la::NCHUNK * la::HD * la::HD];
__device__ float g_cks[(size_t)la::NB * la::NHEADS * la::NCHUNK * la::HD];
__device__ float g_wT[3072 * 1024 + 1024 * 1024];
__device__ float g_xr[(size_t)la::ROWS * la::DIM];   // tf32-rounded x
__device__ float2 g_lut[la::SEQ * 32];

// ---------------- helpers ----------------
__device__ __forceinline__ uint32_t cvt_tf32(float f) {
    uint32_t u;
    asm("cvt.rna.tf32.f32 %0, %1;" : "=r"(u) : "f"(f));
    return u;
}
__device__ __forceinline__ float tf32f(float f) { return __uint_as_float(cvt_tf32(f)); }

__device__ __forceinline__ uint32_t smem_u32(const void* p) {
    uint32_t a;
    asm("{ .reg .u64 t; cvta.to.shared.u64 t, %1; cvt.u32.u64 %0, t; }" : "=r"(a) : "l"(p));
    return a;
}

#define MMA_TF32(c, a, b0, b1)                                              \
    asm volatile("mma.sync.aligned.m16n8k8.row.col.f32.tf32.tf32.f32 "      \
                 "{%0,%1,%2,%3},{%4,%5,%6,%7},{%8,%9},{%0,%1,%2,%3};"       \
                 : "+f"((c)[0]), "+f"((c)[1]), "+f"((c)[2]), "+f"((c)[3])   \
                 : "r"((a)[0]), "r"((a)[1]), "r"((a)[2]), "r"((a)[3]),      \
                   "r"(b0), "r"(b1))

#define CP_ASYNC16(dst, src) \
    asm volatile("cp.async.cg.shared.global [%0], [%1], 16;" :: "r"(dst), "l"(src) : "memory")
#define CP_COMMIT  asm volatile("cp.async.commit_group;" ::: "memory")
#define CP_WAIT1   asm volatile("cp.async.wait_group 1;" ::: "memory")

__device__ __forceinline__ float elu1(float z) {
    return (z > 0.f) ? (z + 1.0f) : expf(z);
}
constexpr float ROPE_SC = 0.35355339059327373f; // 64^(-1/4)

// ============ rope LUT build ==============================================
__global__ void rope_lut_build()
{
    const int n = blockIdx.x, lane = threadIdx.x;
    float pw   = powf(10000.0f, (float)lane * (1.0f / 32.0f));
    float invf = 1.0f / pw;
    float ang  = (float)n * invf;
    float s, c;
    sincosf(ang, &s, &c);
    g_lut[n * 32 + lane] = make_float2(c, s);
}

// ============ pre-round to tf32 ===========================================
__global__ __launch_bounds__(256) void round_tf32_k(const float* __restrict__ src,
                                                    float* __restrict__ dst)
{
    const size_t i = ((size_t)blockIdx.x * 256 + threadIdx.x) * 4;
    float4 v = *(const float4*)(src + i);
    uint4 u = { cvt_tf32(v.x), cvt_tf32(v.y), cvt_tf32(v.z), cvt_tf32(v.w) };
    *(uint4*)(dst + i) = u;
}

// ============ cp.async 3-stage tf32 GEMM: C = A[M,K] @ Bt[N,K]^T ==========
// CTA 128x128, BK=16, 128 threads (4 warps), warp tile 64x64.
// smem stage: A[128][20] + B[128][20] floats = 20480 B; 3 stages = 61440 B.
static constexpr int GC_STR    = 20;
static constexpr int GC_STAGE  = 2 * 128 * GC_STR;   // floats per stage
static constexpr int GC_SMEM   = 3 * GC_STAGE * 4;   // 61440 bytes

__global__ __launch_bounds__(128, 2) void gemm_cp(const float* __restrict__ A,
                                                  const float* __restrict__ Bt,
                                                  float* __restrict__ C,
                                                  int M, int N, int K)
{
    extern __shared__ float smf[];
    const uint32_t sbase = smem_u32(smf);
    const int tid = threadIdx.x;
    const int wid = tid >> 5, lane = tid & 31;
    const int g = lane >> 2, tig = lane & 3;
    const int wm = (wid & 1) * 64, wn = (wid >> 1) * 64;

    const float* Ab = A  + (size_t)blockIdx.y * 128 * K;
    const float* Bb = Bt + (size_t)blockIdx.x * 128 * K;

    // load assignment: thread t loads the full 16-float row t of A and of B
    // (4 x 16B chunks each matrix) -> full 128x16 coverage per stage.
    auto load_stage = [&](int s, int k0) {
        const uint32_t sA = sbase + s * (GC_STAGE * 4);
        const uint32_t sB = sA + 128 * GC_STR * 4;
        const float* ga = Ab + (size_t)tid * K + k0;
        const float* gb = Bb + (size_t)tid * K + k0;
        const uint32_t oa = sA + tid * GC_STR * 4;
        const uint32_t ob = sB + tid * GC_STR * 4;
#pragma unroll
        for (int j = 0; j < 4; j++) {
            CP_ASYNC16(oa + j * 16, ga + j * 4);
            CP_ASYNC16(ob + j * 16, gb + j * 4);
        }
        CP_COMMIT;
    };

    float acc[4][8][4];
#pragma unroll
    for (int mt = 0; mt < 4; mt++)
#pragma unroll
        for (int nt = 0; nt < 8; nt++)
#pragma unroll
            for (int i = 0; i < 4; i++) acc[mt][nt][i] = 0.f;

    load_stage(0, 0);
    load_stage(1, 16);

    const int KT = K >> 4;
    for (int k = 0; k < KT; k++) {
        CP_WAIT1;
        __syncthreads();
        {
            const uint32_t* uA = (const uint32_t*)smf + (k % 3) * GC_STAGE;
            const uint32_t* uB = uA + 128 * GC_STR;
#pragma unroll
            for (int ks = 0; ks < 2; ks++) {
                const int kb = ks * 8;
                uint32_t af[4][4];
#pragma unroll
                for (int mt = 0; mt < 4; mt++) {
                    int r = wm + mt * 16 + g;
                    af[mt][0] = uA[r * GC_STR + kb + tig];
                    af[mt][1] = uA[(r + 8) * GC_STR + kb + tig];
                    af[mt][2] = uA[r * GC_STR + kb + tig + 4];
                    af[mt][3] = uA[(r + 8) * GC_STR + kb + tig + 4];
                }
#pragma unroll
                for (int nt = 0; nt < 8; nt++) {
                    int n = wn + nt * 8 + g;
                    uint32_t b0 = uB[n * GC_STR + kb + tig];
                    uint32_t b1 = uB[n * GC_STR + kb + tig + 4];
#pragma unroll
                    for (int mt = 0; mt < 4; mt++)
                        MMA_TF32(acc[mt][nt], af[mt], b0, b1);
                }
            }
        }
        __syncthreads();
        if (k + 2 < KT) load_stage((k + 2) % 3, (k + 2) << 4);
        else            CP_COMMIT;   // keep group count consistent
    }

    // epilogue
#pragma unroll
    for (int mt = 0; mt < 4; mt++) {
        const int r0 = blockIdx.y * 128 + wm + mt * 16 + g;
#pragma unroll
        for (int nt = 0; nt < 8; nt++) {
            const int col = blockIdx.x * 128 + wn + nt * 8 + tig * 2;
            *(float2*)(C + (size_t)r0 * N + col) =
                make_float2(acc[mt][nt][0], acc[mt][nt][1]);
            *(float2*)(C + (size_t)(r0 + 8) * N + col) =
                make_float2(acc[mt][nt][2], acc[mt][nt][3]);
        }
    }
}

// ---------------- weight transpose (rounds to tf32 at store) ---------------
__global__ __launch_bounds__(256) void transpose_w(const float* __restrict__ src,
                                                   float* __restrict__ dst,
                                                   int R, int Ccols)
{
    __shared__ float t[32][33];
    const int bx = blockIdx.x * 32, by = blockIdx.y * 32;
    const int x = threadIdx.x & 31, y = threadIdx.x >> 5;
#pragma unroll
    for (int i = 0; i < 32; i += 8)
        t[y + i][x] = src[(size_t)(by + y + i) * Ccols + bx + x];
    __syncthreads();
#pragma unroll
    for (int i = 0; i < 32; i += 8)
        dst[(size_t)(bx + y + i) * R + by + x] = tf32f(t[x][y + i]);
}

// ============ chunk_sums: KV_c = K^T @ V (mma), ks = colsum(K) ============
static constexpr int CS_SMEM = 16896 * 4;

__global__ __launch_bounds__(256) void chunk_sums()
{
    extern __shared__ float sm[];
    float* sKT = sm;          // [d][t]
    float* sVT = sm + 8448;   // [m][t]

    const int c  = blockIdx.x;
    const int bh = blockIdx.y;
    const int b  = bh >> 4, h = bh & 15;
    const int tid = threadIdx.x;
    const int wid = tid >> 5, lane = tid & 31;
    const int g = lane >> 2, tig = lane & 3;

    const size_t rowbase = (size_t)(b * la::SEQ + c * la::CHUNK) * 3072 + h * 64;
    const float* kg = g_qkv + rowbase + 1024;
    const float* vg = g_qkv + rowbase + 2048;

#pragma unroll
    for (int i = 0; i < 4; i++) {
        int idx = i * 256 + tid;
        int t = idx >> 3, d0 = (idx & 7) << 2;
        int n = c * la::CHUNK + t;
        float4 ka = *(const float4*)(kg + (size_t)t * 3072 + d0);
        float4 kb = *(const float4*)(kg + (size_t)t * 3072 + d0 + 32);
        float k1[4] = {ka.x, ka.y, ka.z, ka.w};
        float k2[4] = {kb.x, kb.y, kb.z, kb.w};
#pragma unroll
        for (int j = 0; j < 4; j++) {
            float2 cs = g_lut[n * 32 + d0 + j];
            float o1 = (k1[j] * cs.x - k2[j] * cs.y) * ROPE_SC;
            float o2 = (k1[j] * cs.y + k2[j] * cs.x) * ROPE_SC;
            sKT[(d0 + j) * 132 + t]      = tf32f(elu1(o1));
            sKT[(d0 + 32 + j) * 132 + t] = tf32f(elu1(o2));
        }
    }
#pragma unroll
    for (int i = 0; i < 8; i++) {
        int idx = i * 256 + tid;
        int t = idx >> 4, m0 = (idx & 15) << 2;
        float4 v4 = *(const float4*)(vg + (size_t)t * 3072 + m0);
        sVT[(m0 + 0) * 132 + t] = tf32f(v4.x);
        sVT[(m0 + 1) * 132 + t] = tf32f(v4.y);
        sVT[(m0 + 2) * 132 + t] = tf32f(v4.z);
        sVT[(m0 + 3) * 132 + t] = tf32f(v4.w);
    }
    __syncthreads();

    const int wm = (wid & 3) * 16, wn = (wid >> 2) * 32;
    const uint32_t* uK = (const uint32_t*)sKT;
    const uint32_t* uV = (const uint32_t*)sVT;
    float acc[4][4];
#pragma unroll
    for (int nt = 0; nt < 4; nt++)
#pragma unroll
        for (int i = 0; i < 4; i++) acc[nt][i] = 0.f;

#pragma unroll
    for (int ks = 0; ks < 16; ks++) {
        const int kb = ks * 8;
        uint32_t af[4];
        af[0] = uK[(wm + g) * 132 + kb + tig];
        af[1] = uK[(wm + g + 8) * 132 + kb + tig];
        af[2] = uK[(wm + g) * 132 + kb + tig + 4];
        af[3] = uK[(wm + g + 8) * 132 + kb + tig + 4];
#pragma unroll
        for (int nt = 0; nt < 4; nt++) {
            int n = wn + nt * 8 + g;
            uint32_t b0 = uV[n * 132 + kb + tig];
            uint32_t b1 = uV[n * 132 + kb + tig + 4];
            MMA_TF32(acc[nt], af, b0, b1);
        }
    }
    float* outp = g_ckv + ((size_t)bh * la::NCHUNK + c) * 4096;
#pragma unroll
    for (int nt = 0; nt < 4; nt++) {
        int d = wm + g, m = wn + nt * 8 + tig * 2;
        *(float2*)(outp + d * 64 + m)       = make_float2(acc[nt][0], acc[nt][1]);
        *(float2*)(outp + (d + 8) * 64 + m) = make_float2(acc[nt][2], acc[nt][3]);
    }
    if (tid < 64) {
        float s = 0.f;
        for (int t = 0; t < 128; t++) s += sKT[tid * 132 + t];
        g_cks[((size_t)bh * la::NCHUNK + c) * 64 + tid] = s;
    }
}

// ---------------- exclusive prefix over chunks -----------------------------
__global__ __launch_bounds__(256) void prefix_scan()
{
    const int bh  = blockIdx.x;
    const int seg = blockIdx.y;
    const int tid = threadIdx.x;

    float2* base = (float2*)(g_ckv + (size_t)bh * la::NCHUNK * 4096) + seg * 256 + tid;
    float2 vals[la::NCHUNK];
#pragma unroll
    for (int c = 0; c < la::NCHUNK; c++) vals[c] = base[c * 2048];
    float2 run = make_float2(0.f, 0.f);
#pragma unroll
    for (int c = 0; c < la::NCHUNK; c++) {
        float2 t = vals[c];
        vals[c] = run;
        run.x += t.x; run.y += t.y;
    }
#pragma unroll
    for (int c = 0; c < la::NCHUNK; c++) base[c * 2048] = vals[c];

    if (seg == 0 && tid < 64) {
        float* kb = g_cks + (size_t)bh * la::NCHUNK * 64 + tid;
        float kv[la::NCHUNK];
#pragma unroll
        for (int c = 0; c < la::NCHUNK; c++) kv[c] = kb[c * 64];
        float r = 0.f;
#pragma unroll
        for (int c = 0; c < la::NCHUNK; c++) { float t = kv[c]; kv[c] = r; r += t; }
#pragma unroll
        for (int c = 0; c < la::NCHUNK; c++) kb[c * 64] = kv[c];
    }
}

// ============ chunk_out: mma-based intra + inter ==========================
static constexpr int CO_SMEM = 38848 * 4;

__global__ __launch_bounds__(256) void chunk_out()
{
    extern __shared__ float sm[];
    float* sQ   = sm;             // [r][d]
    float* sK   = sm + 8704;      // [t][d] (later sVT)
    float* sVT  = sm + 8704;      // [m][t]
    float* sS   = sm + 17408;     // [r][j]
    float* sKVT = sm + 34304;     // [m][d]
    float* sks  = sm + 38656;
    float* sden = sm + 38720;

    const int c  = blockIdx.x;
    const int bh = blockIdx.y;
    const int b  = bh >> 4, h = bh & 15;
    const int tid = threadIdx.x;
    const int wid = tid >> 5, lane = tid & 31;
    const int g = lane >> 2, tig = lane & 3;

    const size_t rowbase = (size_t)(b * la::SEQ + c * la::CHUNK) * 3072 + h * 64;
    const float* qg = g_qkv + rowbase;
    const float* kg = qg + 1024;
    const float* vg = qg + 2048;

#pragma unroll
    for (int i = 0; i < 4; i++) {
        int idx = i * 256 + tid;
        int t = idx >> 3, d0 = (idx & 7) << 2;
        int n = c * la::CHUNK + t;
        float4 qa = *(const float4*)(qg + (size_t)t * 3072 + d0);
        float4 qb = *(const float4*)(qg + (size_t)t * 3072 + d0 + 32);
        float4 ka = *(const float4*)(kg + (size_t)t * 3072 + d0);
        float4 kb = *(const float4*)(kg + (size_t)t * 3072 + d0 + 32);
        float q1[4] = {qa.x, qa.y, qa.z, qa.w}, q2[4] = {qb.x, qb.y, qb.z, qb.w};
        float k1[4] = {ka.x, ka.y, ka.z, ka.w}, k2[4] = {kb.x, kb.y, kb.z, kb.w};
#pragma unroll
        for (int j = 0; j < 4; j++) {
            float2 cs = g_lut[n * 32 + d0 + j];
            float qo1 = (q1[j] * cs.x - q2[j] * cs.y) * ROPE_SC;
            float qo2 = (q1[j] * cs.y + q2[j] * cs.x) * ROPE_SC;
            sQ[t * 68 + d0 + j]      = tf32f(elu1(qo1));
            sQ[t * 68 + d0 + 32 + j] = tf32f(elu1(qo2));
            float ko1 = (k1[j] * cs.x - k2[j] * cs.y) * ROPE_SC;
            float ko2 = (k1[j] * cs.y + k2[j] * cs.x) * ROPE_SC;
            sK[t * 68 + d0 + j]      = tf32f(elu1(ko1));
            sK[t * 68 + d0 + 32 + j] = tf32f(elu1(ko2));
        }
    }
    const float* kvg = g_ckv + ((size_t)bh * la::NCHUNK + c) * 4096;
#pragma unroll
    for (int i = 0; i < 4; i++) {
        int idx = i * 256 + tid;
        int d = idx >> 4, m0 = (idx & 15) << 2;
        float4 kv4 = *(const float4*)(kvg + d * 64 + m0);
        sKVT[(m0 + 0) * 68 + d] = tf32f(kv4.x);
        sKVT[(m0 + 1) * 68 + d] = tf32f(kv4.y);
        sKVT[(m0 + 2) * 68 + d] = tf32f(kv4.z);
        sKVT[(m0 + 3) * 68 + d] = tf32f(kv4.w);
    }
    if (tid < 64) sks[tid] = g_cks[((size_t)bh * la::NCHUNK + c) * 64 + tid];
    __syncthreads();

    // stage1: S = Qf @ Kf^T
    {
        const int wm = (wid & 3) * 32, wn = (wid >> 2) * 64;
        const uint32_t* uA = (const uint32_t*)sQ;
        const uint32_t* uB = (const uint32_t*)sK;
        float acc[2][8][4];
#pragma unroll
        for (int mt = 0; mt < 2; mt++)
#pragma unroll
            for (int nt = 0; nt < 8; nt++)
#pragma unroll
                for (int i = 0; i < 4; i++) acc[mt][nt][i] = 0.f;
#pragma unroll
        for (int ks = 0; ks < 8; ks++) {
            const int kb = ks * 8;
            uint32_t af[2][4];
#pragma unroll
            for (int mt = 0; mt < 2; mt++) {
                int r = wm + mt * 16 + g;
                af[mt][0] = uA[r * 68 + kb + tig];
                af[mt][1] = uA[(r + 8) * 68 + kb + tig];
                af[mt][2] = uA[r * 68 + kb + tig + 4];
                af[mt][3] = uA[(r + 8) * 68 + kb + tig + 4];
            }
#pragma unroll
            for (int nt = 0; nt < 8; nt++) {
                int n = wn + nt * 8 + g;
                uint32_t b0 = uB[n * 68 + kb + tig];
                uint32_t b1 = uB[n * 68 + kb + tig + 4];
                MMA_TF32(acc[0][nt], af[0], b0, b1);
                MMA_TF32(acc[1][nt], af[1], b0, b1);
            }
        }
        __syncthreads();

#pragma unroll
        for (int mt = 0; mt < 2; mt++) {
            int r0 = wm + mt * 16 + g, r1 = r0 + 8;
#pragma unroll
            for (int nt = 0; nt < 8; nt++) {
                int j0 = wn + nt * 8 + tig * 2;
                float v00 = (j0     <= r0) ? tf32f(acc[mt][nt][0]) : 0.f;
                float v01 = (j0 + 1 <= r0) ? tf32f(acc[mt][nt][1]) : 0.f;
                float v10 = (j0     <= r1) ? tf32f(acc[mt][nt][2]) : 0.f;
                float v11 = (j0 + 1 <= r1) ? tf32f(acc[mt][nt][3]) : 0.f;
                *(float2*)(sS + r0 * 132 + j0) = make_float2(v00, v01);
                *(float2*)(sS + r1 * 132 + j0) = make_float2(v10, v11);
            }
        }
    }
#pragma unroll
    for (int i = 0; i < 8; i++) {
        int idx = i * 256 + tid;
        int t = idx >> 4, m0 = (idx & 15) << 2;
        float4 v4 = *(const float4*)(vg + (size_t)t * 3072 + m0);
        sVT[(m0 + 0) * 132 + t] = tf32f(v4.x);
        sVT[(m0 + 1) * 132 + t] = tf32f(v4.y);
        sVT[(m0 + 2) * 132 + t] = tf32f(v4.z);
        sVT[(m0 + 3) * 132 + t] = tf32f(v4.w);
    }
    __syncthreads();

    if (tid < 128) {
        const int r = tid;
        float s = 0.f;
        for (int j = 0; j < 128; j++) s += sS[r * 132 + j];
        for (int d = 0; d < 64; d++) s = fmaf(sQ[r * 68 + d], sks[d], s);
        sden[r] = fmaxf(s, 1e-6f);
    }
    __syncthreads();

    // stage2: out = S_masked @ V + Qf @ KV^T
    {
        const int wm = (wid & 3) * 32, wn = (wid >> 2) * 32;
        const uint32_t* uS = (const uint32_t*)sS;
        const uint32_t* uV = (const uint32_t*)sVT;
        const uint32_t* uQ = (const uint32_t*)sQ;
        const uint32_t* uKV = (const uint32_t*)sKVT;
        float acc[2][4][4];
#pragma unroll
        for (int mt = 0; mt < 2; mt++)
#pragma unroll
            for (int nt = 0; nt < 4; nt++)
#pragma unroll
                for (int i = 0; i < 4; i++) acc[mt][nt][i] = 0.f;

#pragma unroll
        for (int ks = 0; ks < 16; ks++) {
            const int kb = ks * 8;
            uint32_t af[2][4];
#pragma unroll
            for (int mt = 0; mt < 2; mt++) {
                int r = wm + mt * 16 + g;
                af[mt][0] = uS[r * 132 + kb + tig];
                af[mt][1] = uS[(r + 8) * 132 + kb + tig];
                af[mt][2] = uS[r * 132 + kb + tig + 4];
                af[mt][3] = uS[(r + 8) * 132 + kb + tig + 4];
            }
#pragma unroll
            for (int nt = 0; nt < 4; nt++) {
                int n = wn + nt * 8 + g;
                uint32_t b0 = uV[n * 132 + kb + tig];
                uint32_t b1 = uV[n * 132 + kb + tig + 4];
                MMA_TF32(acc[0][nt], af[0], b0, b1);
                MMA_TF32(acc[1][nt], af[1], b0, b1);
            }
        }
#pragma unroll
        for (int ks = 0; ks < 8; ks++) {
            const int kb = ks * 8;
            uint32_t af[2][4];
#pragma unroll
            for (int mt = 0; mt < 2; mt++) {
                int r = wm + mt * 16 + g;
                af[mt][0] = uQ[r * 68 + kb + tig];
                af[mt][1] = uQ[(r + 8) * 68 + kb + tig];
                af[mt][2] = uQ[r * 68 + kb + tig + 4];
                af[mt][3] = uQ[(r + 8) * 68 + kb + tig + 4];
            }
#pragma unroll
            for (int nt = 0; nt < 4; nt++) {
                int n = wn + nt * 8 + g;
                uint32_t b0 = uKV[n * 68 + kb + tig];
                uint32_t b1 = uKV[n * 68 + kb + tig + 4];
                MMA_TF32(acc[0][nt], af[0], b0, b1);
                MMA_TF32(acc[1][nt], af[1], b0, b1);
            }
        }

        // epilogue: divide, round to tf32 (feeds the pre-rounded GEMM)
#pragma unroll
        for (int mt = 0; mt < 2; mt++) {
            int r0 = wm + mt * 16 + g, r1 = r0 + 8;
            float inv0 = 1.0f / sden[r0];
            float inv1 = 1.0f / sden[r1];
            float* o0 = g_attn + (size_t)(b * la::SEQ + c * la::CHUNK + r0) * 1024 + h * 64;
            float* o1 = g_attn + (size_t)(b * la::SEQ + c * la::CHUNK + r1) * 1024 + h * 64;
#pragma unroll
            for (int nt = 0; nt < 4; nt++) {
                int m = wn + nt * 8 + tig * 2;
                *(float2*)(o0 + m) = make_float2(tf32f(acc[mt][nt][0] * inv0),
                                                 tf32f(acc[mt][nt][1] * inv0));
                *(float2*)(o1 + m) = make_float2(tf32f(acc[mt][nt][2] * inv1),
                                                 tf32f(acc[mt][nt][3] * inv1));
            }
        }
    }
}

// ---------------- launch ----------------
extern "C" void kernel_launch(void* const* d_in, const int* in_sizes, int n_in,
                              void* d_out, int out_size)
{
    const float* x    = (const float*)d_in[0];
    const float* wqkv = (const float*)d_in[1];
    const float* wout = (const float*)d_in[2];
    float*       out  = (float*)d_out;

    float *qkv, *attn, *wT, *xr;
    cudaGetSymbolAddress((void**)&qkv, g_qkv);
    cudaGetSymbolAddress((void**)&attn, g_attn);
    cudaGetSymbolAddress((void**)&wT, g_wT);
    cudaGetSymbolAddress((void**)&xr, g_xr);
    float* wqkvT = wT;
    float* woutT = wT + 3072 * 1024;

    cudaFuncSetAttribute(gemm_cp,    cudaFuncAttributeMaxDynamicSharedMemorySize, GC_SMEM);
    cudaFuncSetAttribute(chunk_sums, cudaFuncAttributeMaxDynamicSharedMemorySize, CS_SMEM);
    cudaFuncSetAttribute(chunk_out,  cudaFuncAttributeMaxDynamicSharedMemorySize, CO_SMEM);

    // 0) rope LUT, tf32-rounded weight transposes, tf32-rounded x
    rope_lut_build<<<la::SEQ, 32>>>();
    transpose_w<<<dim3(3072 / 32, 1024 / 32), 256>>>(wqkv, wqkvT, 1024, 3072);
    transpose_w<<<dim3(1024 / 32, 1024 / 32), 256>>>(wout, woutT, 1024, 1024);
    round_tf32_k<<<la::ROWS * la::DIM / 1024, 256>>>(x, xr);

    // 1) qkv = x @ w_qkv
    gemm_cp<<<dim3(3072 / 128, la::ROWS / 128), 128, GC_SMEM>>>(xr, wqkvT, qkv,
                                                                la::ROWS, 3072, 1024);

    // 2) per-chunk KV sums (rope+elu fused at load)
    dim3 g3(la::NCHUNK, la::NB * la::NHEADS);
    chunk_sums<<<g3, 256, CS_SMEM>>>();

    // 3) exclusive prefix over chunks
    prefix_scan<<<dim3(la::NB * la::NHEADS, 8), 256>>>();

    // 4) per-chunk outputs (rope+elu fused at load; writes tf32-rounded attn)
    chunk_out<<<g3, 256, CO_SMEM>>>();

    // 5) out = attn @ w_out
    gemm_cp<<<dim3(1024 / 128, la::ROWS / 128), 128, GC_SMEM>>>(attn, woutT, out,
                                                                la::ROWS, 1024, 1024);
}